// round 1
// baseline (speedup 1.0000x reference)
#include <cuda_runtime.h>
#include <cstdint>

// LSTM: B=64, T=4096, H=128, input dim 1, gate order i,f,g,o; then Linear(H->1) on h_T.
//
// Design: 64 clusters x 2 CTAs (128 CTAs, 1/SM). Cluster c handles batch c.
// Each CTA owns 64 hidden indices (rank*64 .. rank*64+63) => 256 gate rows.
// All 256x128 fp32 weights live in registers (prepacked as f32x2 pairs).
// Per step: 64x fma.rn.f32x2 per thread against h broadcast from smem,
// gate exchange via smem, new-h pushed to peer CTA via st.shared::cluster,
// one mbarrier (count=64) handshake per step with double-buffered h.

#define B_ 64
#define T_ 4096
#define H_ 128
#define NTHREADS 256

__device__ __forceinline__ uint32_t smem_u32(const void* p) {
    uint32_t a;
    asm("{ .reg .u64 t; cvta.to.shared.u64 t, %1; cvt.u32.u64 %0, t; }" : "=r"(a) : "l"(p));
    return a;
}
__device__ __forceinline__ uint32_t ctarank() {
    uint32_t r; asm("mov.u32 %0, %%cluster_ctarank;" : "=r"(r)); return r;
}
__device__ __forceinline__ uint32_t mapa_u32(uint32_t a, uint32_t rk) {
    uint32_t r; asm("mapa.shared::cluster.u32 %0, %1, %2;" : "=r"(r) : "r"(a), "r"(rk)); return r;
}

__global__ void __launch_bounds__(NTHREADS, 1) __cluster_dims__(2, 1, 1)
lstm_kernel(const float* __restrict__ data, const float* __restrict__ h0,
            const float* __restrict__ c0,   const float* __restrict__ W_ih,
            const float* __restrict__ W_hh, const float* __restrict__ b_ih,
            const float* __restrict__ b_hh, const float* __restrict__ W_out,
            const float* __restrict__ b_out, float* __restrict__ out)
{
    __shared__ __align__(16) float hbuf[2][H_];   // double-buffered hidden state (full H per CTA)
    __shared__ float gates_s[NTHREADS];
    __shared__ __align__(8) unsigned long long mbar;

    const int tid  = threadIdx.x;
    const int q    = tid >> 6;          // gate group: 0=i,1=f,2=g,3=o (uniform per warp-pair)
    const int jl   = tid & 63;
    const uint32_t rank  = ctarank();
    const int batch = blockIdx.x >> 1;
    const int j    = (int)rank * 64 + jl;   // global hidden index this CTA half owns
    const int grow = q * 128 + j;           // gate row in [0,512)

    // ---- load this thread's W_hh row (128 fp32) into registers, prepacked as f32x2 ----
    unsigned long long wpk[64];
    {
        const ulonglong2* wr = reinterpret_cast<const ulonglong2*>(W_hh + (size_t)grow * H_);
        #pragma unroll
        for (int i = 0; i < 32; i++) { ulonglong2 v = wr[i]; wpk[2*i] = v.x; wpk[2*i+1] = v.y; }
    }
    const float wih  = W_ih[grow];
    const float bias = b_ih[grow] + b_hh[grow];

    float c = 0.f;
    if (tid < 64) c = c0[batch * H_ + j];   // tid<64 => q=0, jl=tid, j = rank*64+tid

    if (tid < H_) hbuf[0][tid] = h0[batch * H_ + tid];

    const uint32_t mbar_a   = smem_u32(&mbar);
    const uint32_t hb_a     = smem_u32(&hbuf[0][0]);
    const uint32_t peer     = rank ^ 1u;
    const uint32_t peer_hb  = mapa_u32(hb_a, peer);
    const uint32_t peer_mb  = mapa_u32(mbar_a, peer);

    if (tid == 0) {
        asm volatile("mbarrier.init.shared.b64 [%0], %1;" :: "r"(mbar_a), "r"(64u) : "memory");
    }
    __syncthreads();
    // peer's mbarrier must be live before any remote arrive
    asm volatile("barrier.cluster.arrive.aligned;" ::: "memory");
    asm volatile("barrier.cluster.wait.aligned;"   ::: "memory");

    const float* xp = data + (size_t)batch * T_;

    #pragma unroll 1
    for (int t = 0; t < T_; ++t) {
        const int p = t & 1;
        const float x = __ldg(xp + t);

        // ---- dot(W_hh[grow,:], h)  via packed f32x2 FMAs, h broadcast from smem ----
        const ulonglong2* hp = reinterpret_cast<const ulonglong2*>(&hbuf[p][0]);
        unsigned long long a0 = 0ull, a1 = 0ull, a2 = 0ull, a3 = 0ull;
        #pragma unroll
        for (int i = 0; i < 16; i++) {
            ulonglong2 h2 = hp[2*i];
            asm("fma.rn.f32x2 %0, %1, %2, %0;" : "+l"(a0) : "l"(wpk[4*i    ]), "l"(h2.x));
            asm("fma.rn.f32x2 %0, %1, %2, %0;" : "+l"(a1) : "l"(wpk[4*i + 1]), "l"(h2.y));
            ulonglong2 h3 = hp[2*i + 1];
            asm("fma.rn.f32x2 %0, %1, %2, %0;" : "+l"(a2) : "l"(wpk[4*i + 2]), "l"(h3.x));
            asm("fma.rn.f32x2 %0, %1, %2, %0;" : "+l"(a3) : "l"(wpk[4*i + 3]), "l"(h3.y));
        }
        float s;
        {
            unsigned long long s01, s23, st;
            asm("add.rn.f32x2 %0, %1, %2;" : "=l"(s01) : "l"(a0),  "l"(a1));
            asm("add.rn.f32x2 %0, %1, %2;" : "=l"(s23) : "l"(a2),  "l"(a3));
            asm("add.rn.f32x2 %0, %1, %2;" : "=l"(st)  : "l"(s01), "l"(s23));
            float lo, hi;
            asm("mov.b64 {%0,%1}, %2;" : "=f"(lo), "=f"(hi) : "l"(st));
            s = lo + hi;
        }

        float pre = fmaf(wih, x, s + bias);
        pre = fminf(fmaxf(pre, -30.f), 30.f);
        float act;
        if (q == 2) {                       // tanh (uniform per warp)
            float e = __expf(2.f * pre);
            act = (e - 1.f) / (e + 1.f);
        } else {                            // sigmoid
            act = 1.f / (1.f + __expf(-pre));
        }
        gates_s[tid] = act;
        __syncthreads();

        if (tid < 64) {
            float gi = gates_s[tid];
            float gf = gates_s[64  + tid];
            float gg = gates_s[128 + tid];
            float go = gates_s[192 + tid];
            c = fmaf(gf, c, gi * gg);
            float cc = fminf(fmaxf(c, -30.f), 30.f);
            float e  = __expf(2.f * cc);
            float hn = go * ((e - 1.f) / (e + 1.f));

            const int hidx = (1 ^ p) * H_ + j;
            hbuf[1 ^ p][j] = hn;                                  // local copy
            uint32_t ra = peer_hb + (uint32_t)hidx * 4u;          // peer copy (DSMEM push)
            asm volatile("st.shared::cluster.f32 [%0], %1;" :: "r"(ra), "f"(hn) : "memory");
            // release: orders this thread's remote store before peer's acquire-wait
            asm volatile("mbarrier.arrive.release.cluster.shared::cluster.b64 _, [%0];"
                         :: "r"(peer_mb) : "memory");
        }
        __syncthreads();   // local hbuf[1^p]/gates_s WAR ordering

        // wait for peer's 64 arrivals of this phase (acquire at cluster scope)
        {
            const uint32_t par = (uint32_t)(t & 1);
            asm volatile(
                "{\n\t"
                ".reg .pred P1;\n\t"
                "WLOOP_%=:\n\t"
                "mbarrier.try_wait.parity.acquire.cluster.shared::cta.b64 P1, [%0], %1, 0x989680;\n\t"
                "@P1 bra.uni WDONE_%=;\n\t"
                "bra.uni WLOOP_%=;\n\t"
                "WDONE_%=:\n\t"
                "}"
                :: "r"(mbar_a), "r"(par) : "memory");
        }
    }

    // after t=4095 (p=1), final h lives in hbuf[0]; peer half visible via final acquire-wait
    if (rank == 0 && tid < 32) {
        float s = 0.f;
        #pragma unroll
        for (int m = 0; m < 4; m++)
            s = fmaf(hbuf[0][tid * 4 + m], W_out[tid * 4 + m], s);
        #pragma unroll
        for (int off = 16; off; off >>= 1)
            s += __shfl_xor_sync(0xffffffffu, s, off);
        if (tid == 0) out[batch] = s + b_out[0];
    }

    // do not let a CTA exit while its peer may still touch cluster smem
    asm volatile("barrier.cluster.arrive.aligned;" ::: "memory");
    asm volatile("barrier.cluster.wait.aligned;"   ::: "memory");
}

extern "C" void kernel_launch(void* const* d_in, const int* in_sizes, int n_in,
                              void* d_out, int out_size)
{
    const float* data  = (const float*)d_in[0];
    const float* h0    = (const float*)d_in[1];
    const float* c0    = (const float*)d_in[2];
    const float* W_ih  = (const float*)d_in[3];
    const float* W_hh  = (const float*)d_in[4];
    const float* b_ih  = (const float*)d_in[5];
    const float* b_hh  = (const float*)d_in[6];
    const float* W_out = (const float*)d_in[7];
    const float* b_out = (const float*)d_in[8];
    float* out = (float*)d_out;

    lstm_kernel<<<B_ * 2, NTHREADS>>>(data, h0, c0, W_ih, W_hh, b_ih, b_hh, W_out, b_out, out);
}

// round 2
// speedup vs baseline: 1.8176x; 1.8176x over previous
#include <cuda_runtime.h>
#include <cstdint>

// LSTM: B=64, T=4096, H=128, gates i,f,g,o; Linear(H->1) on h_T.
// 64 clusters x 2 CTAs. Each CTA owns hidden indices [rank*64, rank*64+64).
// Thread map: q = tid&3 (gate), jloc = tid>>2 (hidden idx within half).
// Weights (256 rows x 128 cols per CTA) fully register-resident as f32x2 pairs,
// split into local-column half and remote-column half.
// Per step: shuffle gate-combine (no smem), h exchange to peer via
// st.async + mbarrier complete_tx (256 bytes/phase), local-half dot overlaps
// the DSMEM flight; exactly one __syncthreads per step.

#define B_ 64
#define T_ 4096
#define H_ 128
#define NT 256

__device__ __forceinline__ uint32_t smem_u32(const void* p) {
    uint32_t a;
    asm("{ .reg .u64 t; cvta.to.shared.u64 t, %1; cvt.u32.u64 %0, t; }" : "=r"(a) : "l"(p));
    return a;
}
__device__ __forceinline__ uint32_t ctarank() {
    uint32_t r; asm("mov.u32 %0, %%cluster_ctarank;" : "=r"(r)); return r;
}
__device__ __forceinline__ uint32_t mapa_u32(uint32_t a, uint32_t rk) {
    uint32_t r; asm("mapa.shared::cluster.u32 %0, %1, %2;" : "=r"(r) : "r"(a), "r"(rk)); return r;
}

// 32 packed FMAs (64 floats) of one column-half: W[32] f32x2 pairs vs 16 LDS.128 of h.
#define DOT_HALF(Wp, HP)                                                              \
    _Pragma("unroll")                                                                 \
    for (int i_ = 0; i_ < 8; i_++) {                                                  \
        ulonglong2 h2_ = (HP)[2*i_], h3_ = (HP)[2*i_ + 1];                            \
        asm("fma.rn.f32x2 %0, %1, %2, %0;" : "+l"(a0) : "l"((Wp)[4*i_    ]), "l"(h2_.x)); \
        asm("fma.rn.f32x2 %0, %1, %2, %0;" : "+l"(a1) : "l"((Wp)[4*i_ + 1]), "l"(h2_.y)); \
        asm("fma.rn.f32x2 %0, %1, %2, %0;" : "+l"(a2) : "l"((Wp)[4*i_ + 2]), "l"(h3_.x)); \
        asm("fma.rn.f32x2 %0, %1, %2, %0;" : "+l"(a3) : "l"((Wp)[4*i_ + 3]), "l"(h3_.y)); \
    }

#define MBAR_WAIT(addr, par)                                                          \
    asm volatile(                                                                     \
        "{\n\t"                                                                       \
        ".reg .pred P1;\n\t"                                                          \
        "WL_%=:\n\t"                                                                  \
        "mbarrier.try_wait.parity.acquire.cluster.shared::cta.b64 P1, [%0], %1, 0x989680;\n\t" \
        "@P1 bra.uni WD_%=;\n\t"                                                      \
        "bra.uni WL_%=;\n\t"                                                          \
        "WD_%=:\n\t"                                                                  \
        "}" :: "r"(addr), "r"(par) : "memory")

__global__ void __launch_bounds__(NT, 1) __cluster_dims__(2, 1, 1)
lstm_kernel(const float* __restrict__ data, const float* __restrict__ h0,
            const float* __restrict__ c0,   const float* __restrict__ W_ih,
            const float* __restrict__ W_hh, const float* __restrict__ b_ih,
            const float* __restrict__ b_hh, const float* __restrict__ W_out,
            const float* __restrict__ b_out, float* __restrict__ out)
{
    __shared__ __align__(16) float hbuf[2][H_];   // double-buffered full hidden state
    __shared__ __align__(16) float xs[T_];        // whole input sequence for this batch
    __shared__ __align__(8) unsigned long long mbar;

    const int tid   = threadIdx.x;
    const int q     = tid & 3;            // gate: 0=i,1=f,2=g,3=o (varies within warp)
    const int jloc  = tid >> 2;           // 0..63
    const uint32_t rank = ctarank();
    const int batch = blockIdx.x >> 1;
    const int jglob = (int)rank * 64 + jloc;
    const int grow  = q * H_ + jglob;     // gate row in [0,512)

    // ---- register-resident weights, split by column half ----
    unsigned long long wl[32], wr[32];    // local cols, remote cols (f32x2 pairs)
    {
        const float* row = W_hh + (size_t)grow * H_;
        const ulonglong2* pl = reinterpret_cast<const ulonglong2*>(row + (int)rank * 64);
        const ulonglong2* pr = reinterpret_cast<const ulonglong2*>(row + (int)(rank ^ 1u) * 64);
        #pragma unroll
        for (int i = 0; i < 16; i++) { ulonglong2 v = pl[i]; wl[2*i] = v.x; wl[2*i+1] = v.y; }
        #pragma unroll
        for (int i = 0; i < 16; i++) { ulonglong2 v = pr[i]; wr[2*i] = v.x; wr[2*i+1] = v.y; }
    }
    const float wih  = W_ih[grow];
    const float bias = b_ih[grow] + b_hh[grow];
    const float actA = (q == 2) ? 2.f : 1.f;     // tanh(x) = 2*sigmoid(2x)-1
    const float actB = (q == 2) ? -1.f : 0.f;

    float c = c0[batch * H_ + jglob];     // replicated across the 4 lanes of a group

    if (tid < H_) hbuf[0][tid] = h0[batch * H_ + tid];
    for (int i = tid; i < T_; i += NT) xs[i] = data[(size_t)batch * T_ + i];

    const uint32_t mbar_a  = smem_u32(&mbar);
    const uint32_t hb_a    = smem_u32(&hbuf[0][0]);
    const uint32_t peer    = rank ^ 1u;
    const uint32_t peer_hb = mapa_u32(hb_a, peer);
    const uint32_t peer_mb = mapa_u32(mbar_a, peer);

    if (tid == 0) {
        asm volatile("mbarrier.init.shared.b64 [%0], %1;" :: "r"(mbar_a), "r"(1u) : "memory");
        // complete phase 0 trivially (no tx pending; peer can't st.async before cluster sync)
        asm volatile("mbarrier.arrive.shared.b64 _, [%0];" :: "r"(mbar_a) : "memory");
    }
    __syncthreads();
    asm volatile("barrier.cluster.arrive.aligned;" ::: "memory");
    asm volatile("barrier.cluster.wait.aligned;"   ::: "memory");

    const int locOff = (int)rank * 64;
    const int remOff = (int)peer * 64;
    const int lane   = tid & 31;
    const int b4     = lane & ~3;

    // prologue: local-half partial dot over hbuf[0]
    unsigned long long a0 = 0ull, a1 = 0ull, a2 = 0ull, a3 = 0ull;
    {
        const ulonglong2* hp = reinterpret_cast<const ulonglong2*>(&hbuf[0][locOff]);
        DOT_HALF(wl, hp)
    }

    #pragma unroll 1
    for (int t = 0; t < T_; ++t) {
        const int p  = t & 1;
        const int w2 = p ^ 1;
        const float x = xs[t];                 // hoisted above the wait

        // phase t: remote half of hbuf[p] has arrived
        MBAR_WAIT(mbar_a, (uint32_t)p);
        if (tid == 0) {                        // register next phase's 64x4 bytes
            asm volatile("mbarrier.arrive.expect_tx.shared::cta.b64 _, [%0], %1;"
                         :: "r"(mbar_a), "r"(256u) : "memory");
        }

        // finish the dot with the remote half
        {
            const ulonglong2* hp = reinterpret_cast<const ulonglong2*>(&hbuf[p][remOff]);
            DOT_HALF(wr, hp)
        }
        float s;
        {
            unsigned long long s01, s23, st;
            asm("add.rn.f32x2 %0, %1, %2;" : "=l"(s01) : "l"(a0),  "l"(a1));
            asm("add.rn.f32x2 %0, %1, %2;" : "=l"(s23) : "l"(a2),  "l"(a3));
            asm("add.rn.f32x2 %0, %1, %2;" : "=l"(st)  : "l"(s01), "l"(s23));
            float lo, hi;
            asm("mov.b64 {%0,%1}, %2;" : "=f"(lo), "=f"(hi) : "l"(st));
            s = lo + hi;
        }

        float pre = fmaf(wih, x, s + bias);
        pre = fminf(fmaxf(pre, -30.f), 30.f);
        // branch-free sigmoid/tanh: z = actA*pre; sg = 1/(1+exp(-z)); act = actA*sg + actB
        float z  = pre * actA;
        float e  = __expf(-z);
        float sg = __fdividef(1.f, 1.f + e);
        float act = fmaf(sg, actA, actB);

        // gather the 4 gates of this hidden unit (adjacent lanes)
        float gi = __shfl_sync(0xffffffffu, act, b4);
        float gf = __shfl_sync(0xffffffffu, act, b4 | 1);
        float gg = __shfl_sync(0xffffffffu, act, b4 | 2);
        float go = __shfl_sync(0xffffffffu, act, b4 | 3);

        // all 4 lanes of a group compute identical c / hn (no divergent block)
        c = fmaf(gf, c, gi * gg);
        float cc = fminf(fmaxf(c, -30.f), 30.f);
        float e2 = __expf(-2.f * cc);
        float th = __fdividef(2.f, 1.f + e2) - 1.f;
        float hn = go * th;

        if (q == 0) {
            hbuf[w2][jglob] = hn;                                    // local copy
            uint32_t ra = peer_hb + (uint32_t)(w2 * H_ + jglob) * 4u; // peer copy + tx
            asm volatile(
                "st.async.shared::cluster.mbarrier::complete_tx::bytes.b32 [%0], %1, [%2];"
                :: "r"(ra), "r"(__float_as_uint(hn)), "r"(peer_mb) : "memory");
        }
        __syncthreads();   // local half of hbuf[w2] visible CTA-wide

        // local-half partial dot for the NEXT step (overlaps peer's DSMEM flight)
        a0 = a1 = a2 = a3 = 0ull;
        {
            const ulonglong2* hp = reinterpret_cast<const ulonglong2*>(&hbuf[w2][locOff]);
            DOT_HALF(wl, hp)
        }
    }

    // phase T_ (parity 0): remote half of hbuf[0] (final h) has arrived
    MBAR_WAIT(mbar_a, 0u);

    if (rank == 0 && tid < 32) {
        float s = 0.f;
        #pragma unroll
        for (int m = 0; m < 4; m++)
            s = fmaf(hbuf[0][tid * 4 + m], W_out[tid * 4 + m], s);
        #pragma unroll
        for (int off = 16; off; off >>= 1)
            s += __shfl_xor_sync(0xffffffffu, s, off);
        if (tid == 0) out[batch] = s + b_out[0];
    }

    // no CTA exits while its peer may still write this CTA's smem
    asm volatile("barrier.cluster.arrive.aligned;" ::: "memory");
    asm volatile("barrier.cluster.wait.aligned;"   ::: "memory");
}

extern "C" void kernel_launch(void* const* d_in, const int* in_sizes, int n_in,
                              void* d_out, int out_size)
{
    const float* data  = (const float*)d_in[0];
    const float* h0    = (const float*)d_in[1];
    const float* c0    = (const float*)d_in[2];
    const float* W_ih  = (const float*)d_in[3];
    const float* W_hh  = (const float*)d_in[4];
    const float* b_ih  = (const float*)d_in[5];
    const float* b_hh  = (const float*)d_in[6];
    const float* W_out = (const float*)d_in[7];
    const float* b_out = (const float*)d_in[8];
    float* out = (float*)d_out;

    lstm_kernel<<<B_ * 2, NT>>>(data, h0, c0, W_ih, W_hh, b_ih, b_hh, W_out, b_out, out);
}

// round 3
// speedup vs baseline: 2.0591x; 1.1328x over previous
#include <cuda_runtime.h>
#include <cstdint>

// LSTM: B=64, T=4096, H=128, gates i,f,g,o; Linear(H->1) on h_T.
// 64 clusters x 2 CTAs (128 CTAs, 1/SM). Each CTA owns hidden [rank*64, rank*64+64).
// Thread map: q = tid&3 (gate), jloc = tid>>2. 256 gate rows/CTA, weights fully
// register-resident as f32x2 pairs split into local/remote column halves.
// Per step: local-half dot overlaps the peer DSMEM flight; remote h arrives via
// st.async + mbarrier complete_tx (256B/phase); cta-scope acquire on the wait;
// MUFU.TANH activations; one __syncthreads per step.

#define B_ 64
#define T_ 4096
#define H_ 128
#define NT 256

__device__ __forceinline__ uint32_t smem_u32(const void* p) {
    uint32_t a;
    asm("{ .reg .u64 t; cvta.to.shared.u64 t, %1; cvt.u32.u64 %0, t; }" : "=r"(a) : "l"(p));
    return a;
}
__device__ __forceinline__ uint32_t ctarank() {
    uint32_t r; asm("mov.u32 %0, %%cluster_ctarank;" : "=r"(r)); return r;
}
__device__ __forceinline__ uint32_t mapa_u32(uint32_t a, uint32_t rk) {
    uint32_t r; asm("mapa.shared::cluster.u32 %0, %1, %2;" : "=r"(r) : "r"(a), "r"(rk)); return r;
}
__device__ __forceinline__ float tanh_fast(float x) {
    float y; asm("tanh.approx.f32 %0, %1;" : "=f"(y) : "f"(x)); return y;
}

// 32 packed FMAs (64 floats) of one column-half: W[32] f32x2 pairs vs 16 LDS.128 of h.
#define DOT_HALF(Wp, HP)                                                              \
    _Pragma("unroll")                                                                 \
    for (int i_ = 0; i_ < 8; i_++) {                                                  \
        ulonglong2 h2_ = (HP)[2*i_], h3_ = (HP)[2*i_ + 1];                            \
        asm("fma.rn.f32x2 %0, %1, %2, %0;" : "+l"(a0) : "l"((Wp)[4*i_    ]), "l"(h2_.x)); \
        asm("fma.rn.f32x2 %0, %1, %2, %0;" : "+l"(a1) : "l"((Wp)[4*i_ + 1]), "l"(h2_.y)); \
        asm("fma.rn.f32x2 %0, %1, %2, %0;" : "+l"(a2) : "l"((Wp)[4*i_ + 2]), "l"(h3_.x)); \
        asm("fma.rn.f32x2 %0, %1, %2, %0;" : "+l"(a3) : "l"((Wp)[4*i_ + 3]), "l"(h3_.y)); \
    }

// cta-scope acquire: st.async data is tracked by complete_tx into LOCAL smem,
// same visibility contract as TMA-delivered data (cta acquire suffices).
#define MBAR_WAIT(addr, par)                                                          \
    asm volatile(                                                                     \
        "{\n\t"                                                                       \
        ".reg .pred P1;\n\t"                                                          \
        "WL_%=:\n\t"                                                                  \
        "mbarrier.try_wait.parity.acquire.cta.shared::cta.b64 P1, [%0], %1, 0x989680;\n\t" \
        "@P1 bra.uni WD_%=;\n\t"                                                      \
        "bra.uni WL_%=;\n\t"                                                          \
        "WD_%=:\n\t"                                                                  \
        "}" :: "r"(addr), "r"(par) : "memory")

__global__ void __launch_bounds__(NT, 1) __cluster_dims__(2, 1, 1)
lstm_kernel(const float* __restrict__ data, const float* __restrict__ h0,
            const float* __restrict__ c0,   const float* __restrict__ W_ih,
            const float* __restrict__ W_hh, const float* __restrict__ b_ih,
            const float* __restrict__ b_hh, const float* __restrict__ W_out,
            const float* __restrict__ b_out, float* __restrict__ out)
{
    __shared__ __align__(16) float hbuf[2][H_];   // double-buffered full hidden state
    __shared__ __align__(16) float xs[T_];        // whole input sequence for this batch
    __shared__ __align__(8) unsigned long long mbar;

    const int tid   = threadIdx.x;
    const int q     = tid & 3;            // gate: 0=i,1=f,2=g,3=o
    const int jloc  = tid >> 2;           // 0..63
    const uint32_t rank = ctarank();
    const int batch = blockIdx.x >> 1;
    const int jglob = (int)rank * 64 + jloc;
    const int grow  = q * H_ + jglob;     // gate row in [0,512)

    // ---- register-resident weights, split by column half ----
    unsigned long long wl[32], wr[32];
    {
        const float* row = W_hh + (size_t)grow * H_;
        const ulonglong2* pl = reinterpret_cast<const ulonglong2*>(row + (int)rank * 64);
        const ulonglong2* pr = reinterpret_cast<const ulonglong2*>(row + (int)(rank ^ 1u) * 64);
        #pragma unroll
        for (int i = 0; i < 16; i++) { ulonglong2 v = pl[i]; wl[2*i] = v.x; wl[2*i+1] = v.y; }
        #pragma unroll
        for (int i = 0; i < 16; i++) { ulonglong2 v = pr[i]; wr[2*i] = v.x; wr[2*i+1] = v.y; }
    }
    const float wih  = W_ih[grow];
    const float bias = b_ih[grow] + b_hh[grow];
    // sigmoid(x) = 0.5*tanh(0.5x)+0.5 ; tanh(x) = tanh(x)
    const float sA = (q == 2) ? 1.f : 0.5f;   // input scale
    const float sB = (q == 2) ? 1.f : 0.5f;   // output scale
    const float sC = (q == 2) ? 0.f : 0.5f;   // output offset

    float c = c0[batch * H_ + jglob];     // replicated across 4 lanes of a group

    if (tid < H_) hbuf[0][tid] = h0[batch * H_ + tid];
    for (int i = tid; i < T_; i += NT) xs[i] = data[(size_t)batch * T_ + i];

    const uint32_t mbar_a  = smem_u32(&mbar);
    const uint32_t hb_a    = smem_u32(&hbuf[0][0]);
    const uint32_t peer    = rank ^ 1u;
    const uint32_t peer_hb = mapa_u32(hb_a, peer);
    const uint32_t peer_mb = mapa_u32(mbar_a, peer);

    if (tid == 0) {
        asm volatile("mbarrier.init.shared.b64 [%0], %1;" :: "r"(mbar_a), "r"(1u) : "memory");
        asm volatile("mbarrier.arrive.shared.b64 _, [%0];" :: "r"(mbar_a) : "memory");  // complete phase 0
    }
    __syncthreads();
    asm volatile("barrier.cluster.arrive.aligned;" ::: "memory");
    asm volatile("barrier.cluster.wait.aligned;"   ::: "memory");

    const int locOff = (int)rank * 64;
    const int remOff = (int)peer * 64;
    const int lane   = tid & 31;
    const int b4     = lane & ~3;

    // prologue: local-half partial dot over hbuf[0]
    unsigned long long a0 = 0ull, a1 = 0ull, a2 = 0ull, a3 = 0ull;
    {
        const ulonglong2* hp = reinterpret_cast<const ulonglong2*>(&hbuf[0][locOff]);
        DOT_HALF(wl, hp)
    }

    #pragma unroll 1
    for (int t = 0; t < T_; ++t) {
        const int p  = t & 1;
        const int w2 = p ^ 1;
        const float bx = fmaf(wih, xs[t], bias);   // computed before the wait

        // phase t: remote half of hbuf[p] has arrived
        MBAR_WAIT(mbar_a, (uint32_t)p);
        if (tid == 0) {                            // register next phase's 64x4 bytes
            asm volatile("mbarrier.arrive.expect_tx.shared::cta.b64 _, [%0], %1;"
                         :: "r"(mbar_a), "r"(256u) : "memory");
        }

        // finish the dot with the remote half
        {
            const ulonglong2* hp = reinterpret_cast<const ulonglong2*>(&hbuf[p][remOff]);
            DOT_HALF(wr, hp)
        }
        float s;
        {
            unsigned long long s01, s23, st;
            asm("add.rn.f32x2 %0, %1, %2;" : "=l"(s01) : "l"(a0),  "l"(a1));
            asm("add.rn.f32x2 %0, %1, %2;" : "=l"(s23) : "l"(a2),  "l"(a3));
            asm("add.rn.f32x2 %0, %1, %2;" : "=l"(st)  : "l"(s01), "l"(s23));
            float lo, hi;
            asm("mov.b64 {%0,%1}, %2;" : "=f"(lo), "=f"(hi) : "l"(st));
            s = lo + hi;
        }

        const float pre = s + bx;
        const float act = fmaf(tanh_fast(pre * sA), sB, sC);

        // gather the 4 gates of this hidden unit (adjacent lanes)
        float gi = __shfl_sync(0xffffffffu, act, b4);
        float gf = __shfl_sync(0xffffffffu, act, b4 | 1);
        float gg = __shfl_sync(0xffffffffu, act, b4 | 2);
        float go = __shfl_sync(0xffffffffu, act, b4 | 3);

        c = fmaf(gf, c, gi * gg);
        const float hn = go * tanh_fast(c);

        if (q == 0) {
            hbuf[w2][jglob] = hn;                                     // local copy
            uint32_t ra = peer_hb + (uint32_t)(w2 * H_ + jglob) * 4u; // peer copy + tx
            asm volatile(
                "st.async.shared::cluster.mbarrier::complete_tx::bytes.b32 [%0], %1, [%2];"
                :: "r"(ra), "r"(__float_as_uint(hn)), "r"(peer_mb) : "memory");
        }
        __syncthreads();   // local half of hbuf[w2] visible CTA-wide

        // local-half partial dot for the NEXT step (overlaps peer's DSMEM flight)
        a0 = a1 = a2 = a3 = 0ull;
        {
            const ulonglong2* hp = reinterpret_cast<const ulonglong2*>(&hbuf[w2][locOff]);
            DOT_HALF(wl, hp)
        }
    }

    // phase T_ (parity 0): remote half of hbuf[0] (final h) has arrived
    MBAR_WAIT(mbar_a, 0u);

    if (rank == 0 && tid < 32) {
        float s = 0.f;
        #pragma unroll
        for (int m = 0; m < 4; m++)
            s = fmaf(hbuf[0][tid * 4 + m], W_out[tid * 4 + m], s);
        #pragma unroll
        for (int off = 16; off; off >>= 1)
            s += __shfl_xor_sync(0xffffffffu, s, off);
        if (tid == 0) out[batch] = s + b_out[0];
    }

    // no CTA exits while its peer may still write this CTA's smem
    asm volatile("barrier.cluster.arrive.aligned;" ::: "memory");
    asm volatile("barrier.cluster.wait.aligned;"   ::: "memory");
}

extern "C" void kernel_launch(void* const* d_in, const int* in_sizes, int n_in,
                              void* d_out, int out_size)
{
    const float* data  = (const float*)d_in[0];
    const float* h0    = (const float*)d_in[1];
    const float* c0    = (const float*)d_in[2];
    const float* W_ih  = (const float*)d_in[3];
    const float* W_hh  = (const float*)d_in[4];
    const float* b_ih  = (const float*)d_in[5];
    const float* b_hh  = (const float*)d_in[6];
    const float* W_out = (const float*)d_in[7];
    const float* b_out = (const float*)d_in[8];
    float* out = (float*)d_out;

    lstm_kernel<<<B_ * 2, NT>>>(data, h0, c0, W_ih, W_hh, b_ih, b_hh, W_out, b_out, out);
}